// round 17
// baseline (speedup 1.0000x reference)
#include <cuda_runtime.h>
#include <cstdint>

#define DIMC 64
#define NPIX 512            // 9-bit single-pixel patterns
#define NBINS 4096          // 12-bit pair patterns
#define CHUNKS 8            // 48 rows per hist block, two 24-row passes
#define ROWS_PB 48
#define PASS_ROWS 24
#define LOADS 26            // PASS_ROWS + 2 halo
#define IMG 384
#define WORDS 12            // 384 / 32
#define BATCH 32
#define OUTW 65
#define H_BLOCKS (BATCH * CHUNKS)          // 256
#define NBLOCKS (H_BLOCKS + BATCH)         // 288 <= 296 resident (2/SM structural)

// Static scratch. g_cnt zero at load; per launch: 8 hist blocks REDG-accumulate,
// the image's waiter reads + rezeroes -> replay-deterministic.
// g_done[b]: 0 -> 8 arrivals -> reset to 0 by the waiter.
__device__ int      g_cnt[BATCH][NPIX];    // 64 KB
__device__ unsigned g_done[BATCH];

__global__ __launch_bounds__(384, 2) void mono_kernel(
    const float* __restrict__ alpha,
    const float* __restrict__ w, const float* __restrict__ bias,
    const float* __restrict__ gamma, const float* __restrict__ beta,
    const float* __restrict__ mean, const float* __restrict__ var,
    float* __restrict__ out)
{
    __shared__ int      hist[NBINS];              // 16 KB; waiters overlay floats here
    __shared__ uint32_t bits[LOADS][WORDS + 2];   // ~2.9 KB

    int tid  = threadIdx.x;
    int lane = tid & 31;
    int warp = tid >> 5;

    // ======================= WAITER / CONTRACT role =======================
    if (blockIdx.x >= H_BLOCKS) {
        int b = blockIdx.x - H_BLOCKS;            // image

        float* cnt1 = (float*)hist;               // [0,512)
        float* T    = (float*)hist + 512;         // 3*8*64 = 1536
        float* red  = (float*)hist + 2048;        // 6*64

        // ---- prep BEFORE waiting (overlaps the hist phase) ----
        // nibble tables: T[rr][vv][c] = sum of w[c][3rr+k] over set bits k of vv
        for (int i = tid; i < 3 * 8 * DIMC; i += 384) {
            int rr = i >> 9;                      // 0..2
            int vv = (i >> 6) & 7;
            int c  = i & 63;
            float d = 0.f;
#pragma unroll
            for (int k = 0; k < 3; ++k)
                if ((vv >> k) & 1) d += w[c * 9 + rr * 3 + k];
            T[(rr * 8 + vv) * DIMC + c] = d;
        }
        int c = tid & 63;
        int g = tid >> 6;                         // 0..5
        float A  = gamma[c] * rsqrtf(var[c] + 1e-5f);
        float cb = (bias[c] - mean[c]) * A + beta[c];

        float marker = 0.f;
        if (warp == 2) {
            float av = alpha[lane];
            uint32_t word = __ballot_sync(0xffffffffu, ((int)(av * 255.0f)) & 1);
            marker = (__brev(word) == 0x41493234u) ? 1.0f : 0.0f;   // 'AI24'
        }
        __syncthreads();                          // T[] ready

        // ---- spin until this image's 8 hist blocks have flushed ----
        if (tid == 0) {
            volatile unsigned* gd = &g_done[b];
            while (*gd != (unsigned)CHUNKS) __nanosleep(64);
            g_done[b] = 0;                        // reset for next replay
        }
        __syncthreads();
        __threadfence();                          // acquire

        // combined counts (L2-hot), rezero for replay; fold 1/(H*W)
        for (int n = tid; n < NPIX; n += 384) {
            int s = __ldcg(&g_cnt[b][n]);
            __stcg(&g_cnt[b][n], 0);
            cnt1[n] = (float)s * (1.0f / (384.0f * 384.0f));
        }
        __syncthreads();

        // contract: 512 bins x 64 ch, 3 LDS + relu(bn) + fma per (bin,c)
        float acc = 0.f;
        for (int bin = g; bin < NPIX; bin += 6) {
            float d = T[(bin & 7) * DIMC + c]
                    + T[(8  + ((bin >> 3) & 7)) * DIMC + c]
                    + T[(16 + (bin >> 6)) * DIMC + c];
            float val = fmaxf(fmaf(A, d, cb), 0.f);
            acc = fmaf(cnt1[bin], val, acc);
        }
        red[g * DIMC + c] = acc;
        __syncthreads();

        if (tid < DIMC)
            out[b * OUTW + tid] = red[0 * DIMC + tid] + red[1 * DIMC + tid]
                                + red[2 * DIMC + tid] + red[3 * DIMC + tid]
                                + red[4 * DIMC + tid] + red[5 * DIMC + tid];
        if (warp == 2 && lane == 0)
            out[b * OUTW + DIMC] = marker;
        return;
    }

    // ======================= HIST role (identical to R16) =======================
    int b     = blockIdx.x / CHUNKS;
    int chunk = blockIdx.x % CHUNKS;

    for (int i = tid; i < NBINS; i += 384) hist[i] = 0;
    if (tid < LOADS) { bits[tid][0] = 0u; bits[tid][WORDS + 1] = 0u; }

    const float* img = alpha + (size_t)b * IMG * IMG;
    int r  = tid / WORDS;     // 0..31; active for pairs when r < 24
    int wd = tid % WORDS;

#pragma unroll
    for (int pass = 0; pass < 2; ++pass) {
        int rb = chunk * ROWS_PB + pass * PASS_ROWS;

        // batched loads (MLP=26), then ballots
        float v[LOADS];
#pragma unroll
        for (int row = 0; row < LOADS; ++row) {
            int g = rb - 1 + row;
            v[row] = (g >= 0 && g < IMG) ? img[g * IMG + warp * 32 + lane] : 0.0f;
        }
#pragma unroll
        for (int row = 0; row < LOADS; ++row) {
            uint32_t wb = __ballot_sync(0xffffffffu, ((int)(v[row] * 255.0f)) & 1);
            if (lane == 0) bits[row][warp + 1] = wb;
        }
        __syncthreads();

        if (r < PASS_ROWS) {
            uint32_t p0 = bits[r][wd],     c0 = bits[r][wd + 1],     x0 = bits[r][wd + 2];
            uint32_t p1 = bits[r + 1][wd], c1 = bits[r + 1][wd + 1], x1 = bits[r + 1][wd + 2];
            uint32_t p2 = bits[r + 2][wd], c2 = bits[r + 2][wd + 1], x2 = bits[r + 2][wd + 2];

            {   // pair k=0: window straddles previous word
                uint32_t n0 = __funnelshift_r(p0, c0, 31) & 0xF;
                uint32_t n1 = __funnelshift_r(p1, c1, 31) & 0xF;
                uint32_t n2 = __funnelshift_r(p2, c2, 31) & 0xF;
                atomicAdd(&hist[n0 | (n1 << 4) | (n2 << 8)], 1);
            }
#pragma unroll
            for (int k = 1; k < 16; ++k) {
                uint32_t n0 = __funnelshift_r(c0, x0, 2 * k - 1) & 0xF;
                uint32_t n1 = __funnelshift_r(c1, x1, 2 * k - 1) & 0xF;
                uint32_t n2 = __funnelshift_r(c2, x2, 2 * k - 1) & 0xF;
                atomicAdd(&hist[n0 | (n1 << 4) | (n2 << 8)], 1);
            }
        }
        __syncthreads();   // protect bits[] before next pass
    }

    // gather-marginalize 4096 pair bins -> 512 pixel bins, REDG flush
    for (int n = tid; n < NPIX; n += 384) {
        uint32_t nb = (n & 7) | ((n & 0x38) << 1) | ((n & 0x1C0) << 2);
        int s = 0;
#pragma unroll
        for (int j = 0; j < 8; ++j) {
            uint32_t off = ((j & 1) << 3) | ((j & 2) << 6) | ((j & 4) << 9);
            s += hist[nb | off];                 // A side
            s += hist[(nb << 1) | (off >> 3)];   // B side
        }
        atomicAdd(&g_cnt[b][n], s);              // REDG, no return
    }

    // release: REDs visible before done-counter increment
    __threadfence();
    __syncthreads();
    if (tid == 0) atomicAdd(&g_done[b], 1u);
}

// ---------------------------------------------------------------------------
extern "C" void kernel_launch(void* const* d_in, const int* in_sizes, int n_in,
                              void* d_out, int out_size)
{
    const float* alpha  = (const float*)d_in[0];
    const float* conv_w = (const float*)d_in[1];
    const float* conv_b = (const float*)d_in[2];
    const float* bn_g   = (const float*)d_in[3];
    const float* bn_b   = (const float*)d_in[4];
    const float* bn_m   = (const float*)d_in[5];
    const float* bn_v   = (const float*)d_in[6];
    float* out = (float*)d_out;

    mono_kernel<<<NBLOCKS, 384>>>(
        alpha, conv_w, conv_b, bn_g, bn_b, bn_m, bn_v, out);
}